// round 15
// baseline (speedup 1.0000x reference)
#include <cuda_runtime.h>
#include <cuda_fp16.h>
#include <math.h>

// Radon forward projection, 512x512 img -> [512,512] sinogram (both axes flipped).
// R14: QUARTER-step sheared fp16x2 quad tables (residual lane row-slope <=0.125,
//      kn4 in [-4,4], 18 tables, 60.6 MB), dest-major coalesced table build,
//      launch_bounds(256,6) to restore load batching (MLP).
//      Inner loop: one LDG.64 per bilinear sample, HFMA2 y-blend, fp32 x-blend.

#define IMG_N   512
#define N_ANG   512
#define N_DET   512
#define N_SAMP  256

#define PAD     3
#define TW      (IMG_N + 2*PAD + 2)     // 520

// rows per table by |kn4|: 520 + ceil(|kn4|*519/4), rounded up a bit
// kn4: -4   -3   -2   -1   0    1    2    3    4
// rows:1040  910  780  650  520  650  780  910  1040   => 7280 per orient
#define TOT_ROWS 14560

__device__ uint2 g_tabs[TOT_ROWS * TW];     // 60.6 MB

// per (orient, kn4+4)
__device__ __constant__ int c_rowstart[18] = {
    0, 1040, 1950, 2730, 3380, 3900, 4550, 5330, 6240,
    7280, 8320, 9230, 10010, 10660, 11180, 11830, 12610, 13520
};
__device__ __constant__ int c_rows[9] = {1040, 910, 780, 650, 520, 650, 780, 910, 1040};
__device__ __constant__ int c_off4[9] = {519, 390, 260, 130, 0, 0, 0, 0, 0};

struct __align__(16) AngRec {
    float Ax, Bx, Ay, By;       // x0p = sx*Ax+Bx ; y0p = sx*Ay+By (post-swap)
    float dxp, dyp, idx_, idy_; // step deltas + reciprocals (post-swap)
    int   kn4, base, pad0, pad1;
};
__device__ AngRec g_ang[N_ANG];

__device__ __forceinline__ unsigned h2_bits(__half2 h)
{
    return *reinterpret_cast<unsigned*>(&h);
}
__device__ __forceinline__ __half2 bits_h2(unsigned u)
{
    return *reinterpret_cast<__half2*>(&u);
}

__device__ __forceinline__ void make_angrec(int a)
{
    const float ang = fmaf((float)a, (float)(M_PI / 511.0), (float)(M_PI / 2.0));
    const float sa = sinf(ang);
    const float ca = cosf(ang);
    const float SQRT2 = 1.41421356237309515f;

    float Ax = 255.5f * ca;
    float Bx = fmaf(SQRT2 * sa, 255.5f, 255.5f + (float)PAD);
    float Ay = 255.5f * sa;
    float By = fmaf(-SQRT2 * ca, 255.5f, 255.5f + (float)PAD);
    float dxp = -2.0f * SQRT2 * sa * (255.5f / 256.0f);
    float dyp =  2.0f * SQRT2 * ca * (255.5f / 256.0f);

    const int orient = (fabsf(sa) > fabsf(ca)) ? 1 : 0;
    float cxp = ca, cyp = sa;
    if (orient) {
        float t;
        t = Ax; Ax = Ay; Ay = t;
        t = Bx; Bx = By; By = t;
        t = dxp; dxp = dyp; dyp = t;
        cxp = sa; cyp = ca;
    }

    int kn4 = __float2int_rn(-4.0f * cyp / cxp);
    kn4 = max(-4, min(4, kn4));

    AngRec r;
    r.Ax = Ax; r.Bx = Bx; r.Ay = Ay; r.By = By;
    r.dxp = dxp; r.dyp = dyp;
    r.idx_ = (dxp != 0.0f) ? (1.0f / dxp) : 1.0e30f;
    r.idy_ = (dyp != 0.0f) ? (1.0f / dyp) : 1.0e30f;
    r.kn4 = kn4;
    r.base = (c_rowstart[orient * 9 + (kn4 + 4)] + c_off4[kn4 + 4]) * TW;
    r.pad0 = 0; r.pad1 = 0;
    g_ang[a] = r;
}

// ---------------- dest-major table build (coalesced stores) ----------------
// grid: (17, 33, 18). Table z: orient = z/9, kn4 = z%9-4. Each block fills a
// 32x32 destination tile; loads the needed source patch into smem.
__global__ __launch_bounds__(256) void build_tables(const float* __restrict__ img)
{
    __shared__ float sm[2304];

    const int t   = blockIdx.z;
    const int orient = t / 9;
    const int ki  = t % 9;
    const int k4  = ki - 4;
    const int Rt  = c_rows[ki];
    const int off = c_off4[ki];
    const int tstart = c_rowstart[t];

    const int tx  = threadIdx.x;             // 0..31
    const int ty  = threadIdx.y;             // 0..7
    const int tid = ty * 32 + tx;

    // fuse per-angle precompute into one block
    if (t == 0 && blockIdx.x == 0 && blockIdx.y == 0) {
        make_angrec(tid);
        make_angrec(tid + 256);
    }

    const int r0 = blockIdx.y * 32;
    if (r0 >= Rt) return;
    const int c0 = blockIdx.x * 32;

    // shear-shift bounds over this block's columns (sh monotone in c)
    const int cl = min(c0 + 31, TW - 1);
    const int sA = (k4 * c0) >> 2;
    const int sB = (k4 * cl) >> 2;
    const int shmin = min(sA, sB);
    const int shmax = max(sA, sB);
    const int pymin = r0 - off - shmax;
    const int SH = (r0 + 31 - off - shmin) - pymin + 2;   // img-row count <= 64

    // load source patch (zero-padded)
    if (orient == 0) {
        // sm[li][lj], stride 35: img row = pymin-PAD+li (SH vals), col = c0-PAD+lj (34 vals)
        for (int idx = tid; idx < SH * 34; idx += 256) {
            const int li = idx / 34, lj = idx - li * 34;
            const int rr = pymin - PAD + li, cc = c0 - PAD + lj;
            const bool v = ((unsigned)rr < (unsigned)IMG_N) && ((unsigned)cc < (unsigned)IMG_N);
            sm[li * 35 + lj] = v ? img[rr * IMG_N + cc] : 0.0f;
        }
    } else {
        // sm[li][lj], stride 67: img row = c0-PAD+li (34 vals), col = pymin-PAD+lj (SH vals)
        for (int idx = tid; idx < 34 * 64; idx += 256) {
            const int li = idx >> 6, lj = idx & 63;
            if (lj < SH) {
                const int rr = c0 - PAD + li, cc = pymin - PAD + lj;
                const bool v = ((unsigned)rr < (unsigned)IMG_N) && ((unsigned)cc < (unsigned)IMG_N);
                sm[li * 67 + lj] = v ? img[rr * IMG_N + cc] : 0.0f;
            }
        }
    }
    __syncthreads();

    const int c = c0 + tx;
    if (c >= TW) return;
    const int sh = (k4 * c) >> 2;

    #pragma unroll
    for (int k = 0; k < 4; ++k) {
        const int rp = r0 + ty + 8 * k;
        const int py = rp - off - sh;
        if (rp < Rt && (unsigned)py < (unsigned)TW) {
            const int l = py - pymin;         // 0 .. SH-2
            uint2 q;
            if (orient == 0) {
                q.x = h2_bits(__floats2half2_rn(sm[l * 35 + tx],       sm[l * 35 + tx + 1]));
                q.y = h2_bits(__floats2half2_rn(sm[(l + 1) * 35 + tx], sm[(l + 1) * 35 + tx + 1]));
            } else {
                q.x = h2_bits(__floats2half2_rn(sm[tx * 67 + l],       sm[(tx + 1) * 67 + l]));
                q.y = h2_bits(__floats2half2_rn(sm[tx * 67 + l + 1],   sm[(tx + 1) * 67 + l + 1]));
            }
            g_tabs[(tstart + rp) * TW + c] = q;   // coalesced STG.64
        }
    }
}

// ---------------- radon ----------------
__device__ __forceinline__ void sample_one(
    const uint2* __restrict__ tp, float x, float y, int k4, float& sum)
{
    const float xf = floorf(x);
    const float yf = floorf(y);
    const float fx = x - xf;
    const float fy = y - yf;
    const int ix = (int)xf;
    const int iy = (int)yf;

    const int idx = (iy + ((k4 * ix) >> 2)) * TW + ix;

    const uint2 qh = __ldg(tp + idx);
    const __half2 t = bits_h2(qh.x);            // (q00, q01)
    const __half2 b = bits_h2(qh.y);            // (q10, q11)
    const __half2 fy2 = __float2half2_rn(fy);
    const __half2 m = __hfma2(fy2, __hsub2(b, t), t);   // y-blend both columns
    const float2 mf = __half22float2(m);

    sum += fmaf(fx, mf.y - mf.x, mf.x);
}

__device__ __forceinline__ float integrate(
    const uint2* __restrict__ tp,
    float x0p, float y0p, float dxp, float dyp,
    int s0, int s1, int k4)
{
    float sum = 0.0f;
    const int n = s1 - s0 + 1;
    float sbf = (float)s0;                    // exact
    int i = 0;

    for (; i + 8 <= n; i += 8) {
        const float xb = fmaf(sbf, dxp, x0p); // exact integer base -> no drift
        const float yb = fmaf(sbf, dyp, y0p);
        sbf += 8.0f;
        #pragma unroll
        for (int j = 0; j < 8; ++j) {
            const float x = fmaf((float)j, dxp, xb);   // FFMA-imm
            const float y = fmaf((float)j, dyp, yb);
            sample_one(tp, x, y, k4, sum);
        }
    }
    if (i < n) {
        const float xb = fmaf(sbf, dxp, x0p);
        const float yb = fmaf(sbf, dyp, y0p);
        for (int j = 0; i + j < n; ++j) {
            const float x = fmaf((float)j, dxp, xb);
            const float y = fmaf((float)j, dyp, yb);
            sample_one(tp, x, y, k4, sum);
        }
    }
    return sum;
}

__global__ __launch_bounds__(256, 6) void radon_fwd_kernel(float* __restrict__ out)
{
    const int widx = threadIdx.x >> 5;
    const int lane = threadIdx.x & 31;
    const int wg   = blockIdx.x * 8 + widx;   // 0..16383

    const int h   = wg & 1;                   // s-half
    const int rid = wg >> 1;                  // 0..8191

    const int a     = (rid * 341) & 511;      // angle permutation (balance)
    const int chunk = rid >> 9;               // 0..15
    const int d     = chunk * 32 + lane;      // detector

    const AngRec r = g_ang[a];                // warp-uniform load

    const float sx  = fmaf((float)d, 2.0f / 511.0f, -1.0f);
    const float x0p = fmaf(sx, r.Ax, r.Bx);
    const float y0p = fmaf(sx, r.Ay, r.By);

    // clip sample range to table interior [1, 517] via reciprocal multiplies
    const float L = 1.0f, H = (float)(TW - 3);
    float lo = 0.0f, hi = (float)(N_SAMP - 1);
    {
        const float t0 = (L - x0p) * r.idx_;
        const float t1 = (H - x0p) * r.idx_;
        lo = fmaxf(lo, fminf(t0, t1));
        hi = fminf(hi, fmaxf(t0, t1));
        const float u0 = (L - y0p) * r.idy_;
        const float u1 = (H - y0p) * r.idy_;
        lo = fmaxf(lo, fminf(u0, u1));
        hi = fminf(hi, fmaxf(u0, u1));
    }
    int s0 = (lo > 0.0f) ? (int)ceilf(lo) : 0;
    int s1 = (hi < (float)(N_SAMP - 1)) ? (int)floorf(hi) : (N_SAMP - 1);

    const int hs0 = h * (N_SAMP / 2);
    const int hs1 = hs0 + (N_SAMP / 2) - 1;
    s0 = max(s0, hs0);
    s1 = min(s1, hs1);
    if (s0 > s1) return;

    const uint2* tp = g_tabs + r.base;

    const float sum = integrate(tp, x0p, y0p, r.dxp, r.dyp, s0, s1, r.kn4);

    const int o = (N_ANG - 1 - a) * N_DET + (N_DET - 1 - d);
    atomicAdd(out + o, sum * (1.0f / (float)N_SAMP));
}

extern "C" void kernel_launch(void* const* d_in, const int* in_sizes, int n_in,
                              void* d_out, int out_size)
{
    const float* img = (const float*)d_in[0];
    float* out = (float*)d_out;

    cudaMemsetAsync(out, 0, N_ANG * N_DET * sizeof(float));

    dim3 bt(32, 8);
    dim3 bg(17, 33, 18);                       // col tiles x row tiles x tables
    build_tables<<<bg, bt>>>(img);

    // 512 angles * 16 det-warps * 2 s-halves = 16384 warps = 2048 blocks of 256
    radon_fwd_kernel<<<2048, 256>>>(out);
}

// round 16
// speedup vs baseline: 1.1619x; 1.1619x over previous
#include <cuda_runtime.h>
#include <cuda_fp16.h>
#include <math.h>

// Radon forward projection, 512x512 img -> [512,512] sinogram (both axes flipped).
// R15: half-shear fp16x2 quad tables (10 tables, 35 MB — cheap build), s-split
//      x4 for wave-tail smoothing (4096 blocks), launch_bounds(256,6) for load
//      batching, memset folded into the build kernel, fused angle precompute.
//      Inner loop: one LDG.64 per bilinear sample, HFMA2 y-blend.

#define IMG_N   512
#define N_ANG   512
#define N_DET   512
#define N_SAMP  256

#define PAD     3
#define TW      (IMG_N + 2*PAD + 2)     // 520

#define TOT_ROWS 8320                   // 2 orients x (1040+780+520+780+1040)

// entry: .x = half2(q00,q01) (top row), .y = half2(q10,q11) (bottom row)
__device__ uint2 g_tabs[TOT_ROWS * TW];     // 34.6 MB

// row starts for (orient, kn): orient*5 + (kn+2)
__device__ __constant__ int c_rowstart[10] =
    {0, 1040, 1820, 2340, 3120,  4160, 5200, 5980, 6500, 7280};
__device__ __constant__ int c_off[5] = {519, 260, 0, 0, 0};

struct __align__(16) AngRec {
    float Ax, Bx, Ay, By;       // x0p = sx*Ax+Bx ; y0p = sx*Ay+By (post-swap)
    float dxp, dyp, idx_, idy_; // step deltas + reciprocals (post-swap)
    int   kn, base, pad0, pad1;
};
__device__ AngRec g_ang[N_ANG];

__device__ __forceinline__ unsigned h2_bits(__half2 h)
{
    return *reinterpret_cast<unsigned*>(&h);
}
__device__ __forceinline__ __half2 bits_h2(unsigned u)
{
    return *reinterpret_cast<__half2*>(&u);
}

__device__ __forceinline__ void make_angrec(int a)
{
    const float ang = fmaf((float)a, (float)(M_PI / 511.0), (float)(M_PI / 2.0));
    const float sa = sinf(ang);
    const float ca = cosf(ang);
    const float SQRT2 = 1.41421356237309515f;

    float Ax = 255.5f * ca;
    float Bx = fmaf(SQRT2 * sa, 255.5f, 255.5f + (float)PAD);
    float Ay = 255.5f * sa;
    float By = fmaf(-SQRT2 * ca, 255.5f, 255.5f + (float)PAD);
    float dxp = -2.0f * SQRT2 * sa * (255.5f / 256.0f);
    float dyp =  2.0f * SQRT2 * ca * (255.5f / 256.0f);

    const int orient = (fabsf(sa) > fabsf(ca)) ? 1 : 0;
    float cxp = ca, cyp = sa;
    if (orient) {
        float t;
        t = Ax; Ax = Ay; Ay = t;
        t = Bx; Bx = By; By = t;
        t = dxp; dxp = dyp; dyp = t;
        cxp = sa; cyp = ca;
    }

    int kn = __float2int_rn(-2.0f * cyp / cxp);
    kn = max(-2, min(2, kn));

    AngRec r;
    r.Ax = Ax; r.Bx = Bx; r.Ay = Ay; r.By = By;
    r.dxp = dxp; r.dyp = dyp;
    r.idx_ = (dxp != 0.0f) ? (1.0f / dxp) : 1.0e30f;
    r.idy_ = (dyp != 0.0f) ? (1.0f / dyp) : 1.0e30f;
    r.kn = kn;
    r.base = (c_rowstart[orient * 5 + (kn + 2)] + c_off[kn + 2]) * TW;
    r.pad0 = 0; r.pad1 = 0;
    g_ang[a] = r;
}

// ---------------- fused table + angle build + out zeroing ----------------
__global__ __launch_bounds__(256) void build_tables(const float* __restrict__ img,
                                                    float* __restrict__ out)
{
    __shared__ float sm[34 * 35];

    const int tx = threadIdx.x;              // 0..31
    const int ty = threadIdx.y;              // 0..7
    const int tid = ty * 32 + tx;
    const int bid = blockIdx.y * gridDim.x + blockIdx.x;   // 0..288

    // zero the output (folded memset): 289 blocks x 256 threads cover 262144
    for (int i = bid * 256 + tid; i < N_ANG * N_DET; i += 289 * 256)
        out[i] = 0.0f;

    // block (0,0) also fills the per-angle table (2 angles per thread)
    if (bid == 0) {
        make_angrec(tid);
        make_angrec(tid + 256);
    }

    const int base_r = blockIdx.y * 32 - PAD;
    const int base_c = blockIdx.x * 32 - PAD;

    for (int idx = tid; idx < 34 * 34; idx += 256) {
        const int li = idx / 34, lj = idx % 34;
        const int r = base_r + li, c = base_c + lj;
        const bool v = ((unsigned)r < (unsigned)IMG_N) && ((unsigned)c < (unsigned)IMG_N);
        sm[li * 35 + lj] = v ? img[r * IMG_N + c] : 0.0f;
    }
    __syncthreads();

    #pragma unroll
    for (int k = 0; k < 4; ++k) {
        const int i = ty + 8 * k;            // local row 0..31

        // ---- orient 0: table tile (row=by, col=bx) ----
        const int py = blockIdx.y * 32 + i;
        const int px = blockIdx.x * 32 + tx;
        if (py < TW && px < TW) {
            uint2 q;
            q.x = h2_bits(__floats2half2_rn(sm[i * 35 + tx],       sm[i * 35 + tx + 1]));
            q.y = h2_bits(__floats2half2_rn(sm[(i + 1) * 35 + tx], sm[(i + 1) * 35 + tx + 1]));
            #pragma unroll
            for (int kn = -2; kn <= 2; ++kn) {
                const int row = c_rowstart[kn + 2] + c_off[kn + 2]
                              + py + ((kn * px) >> 1);
                g_tabs[row * TW + px] = q;
            }
        }

        // ---- orient 1 (transposed img): table tile (row=bx, col=by) ----
        const int py2 = blockIdx.x * 32 + i;
        const int px2 = blockIdx.y * 32 + tx;
        if (py2 < TW && px2 < TW) {
            uint2 q;                         // zT(r,c)=z(c,r): transposed smem read
            q.x = h2_bits(__floats2half2_rn(sm[tx * 35 + i],     sm[(tx + 1) * 35 + i]));
            q.y = h2_bits(__floats2half2_rn(sm[tx * 35 + i + 1], sm[(tx + 1) * 35 + i + 1]));
            #pragma unroll
            for (int kn = -2; kn <= 2; ++kn) {
                const int row = c_rowstart[5 + kn + 2] + c_off[kn + 2]
                              + py2 + ((kn * px2) >> 1);
                g_tabs[row * TW + px2] = q;
            }
        }
    }
}

// ---------------- radon ----------------
template<bool ODD>
__device__ __forceinline__ void sample_one(
    const uint2* __restrict__ tp, float x, float y, int M, int kn, float& sum)
{
    const float xf = floorf(x);
    const float yf = floorf(y);
    const float fx = x - xf;
    const float fy = y - yf;
    const int ix = (int)xf;
    const int iy = (int)yf;

    int idx;
    if (ODD) idx = (iy + ((kn * ix) >> 1)) * TW + ix;
    else     idx = iy * TW + ix * M;

    const uint2 qh = __ldg(tp + idx);
    const __half2 t = bits_h2(qh.x);            // (q00, q01)
    const __half2 b = bits_h2(qh.y);            // (q10, q11)
    const __half2 fy2 = __float2half2_rn(fy);
    const __half2 m = __hfma2(fy2, __hsub2(b, t), t);   // y-blend both columns
    const float2 mf = __half22float2(m);

    sum += fmaf(fx, mf.y - mf.x, mf.x);
}

template<bool ODD>
__device__ __forceinline__ float integrate(
    const uint2* __restrict__ tp,
    float x0p, float y0p, float dxp, float dyp,
    int s0, int s1, int M, int kn)
{
    float sum = 0.0f;
    const int n = s1 - s0 + 1;
    float sbf = (float)s0;                    // exact
    int i = 0;

    for (; i + 8 <= n; i += 8) {
        const float xb = fmaf(sbf, dxp, x0p); // exact integer base -> no drift
        const float yb = fmaf(sbf, dyp, y0p);
        sbf += 8.0f;
        #pragma unroll
        for (int j = 0; j < 8; ++j) {
            const float x = fmaf((float)j, dxp, xb);   // FFMA-imm
            const float y = fmaf((float)j, dyp, yb);
            sample_one<ODD>(tp, x, y, M, kn, sum);
        }
    }
    if (i < n) {
        const float xb = fmaf(sbf, dxp, x0p);
        const float yb = fmaf(sbf, dyp, y0p);
        for (int j = 0; i + j < n; ++j) {
            const float x = fmaf((float)j, dxp, xb);
            const float y = fmaf((float)j, dyp, yb);
            sample_one<ODD>(tp, x, y, M, kn, sum);
        }
    }
    return sum;
}

__global__ __launch_bounds__(256, 6) void radon_fwd_kernel(float* __restrict__ out)
{
    const int widx = threadIdx.x >> 5;
    const int lane = threadIdx.x & 31;
    const int wg   = blockIdx.x * 8 + widx;   // 0..32767

    const int h   = wg & 3;                   // s-quarter
    const int rid = wg >> 2;                  // 0..8191

    const int a     = (rid * 341) & 511;      // angle permutation (balance)
    const int chunk = rid >> 9;               // 0..15
    const int d     = chunk * 32 + lane;      // detector

    const AngRec r = g_ang[a];                // warp-uniform load

    const float sx  = fmaf((float)d, 2.0f / 511.0f, -1.0f);
    const float x0p = fmaf(sx, r.Ax, r.Bx);
    const float y0p = fmaf(sx, r.Ay, r.By);

    // clip sample range to table interior [1, 517] via reciprocal multiplies
    const float L = 1.0f, H = (float)(TW - 3);
    float lo = 0.0f, hi = (float)(N_SAMP - 1);
    {
        const float t0 = (L - x0p) * r.idx_;
        const float t1 = (H - x0p) * r.idx_;
        lo = fmaxf(lo, fminf(t0, t1));
        hi = fminf(hi, fmaxf(t0, t1));
        const float u0 = (L - y0p) * r.idy_;
        const float u1 = (H - y0p) * r.idy_;
        lo = fmaxf(lo, fminf(u0, u1));
        hi = fminf(hi, fmaxf(u0, u1));
    }
    int s0 = (lo > 0.0f) ? (int)ceilf(lo) : 0;
    int s1 = (hi < (float)(N_SAMP - 1)) ? (int)floorf(hi) : (N_SAMP - 1);

    // restrict to this warp's s-quarter
    const int hs0 = h * (N_SAMP / 4);
    const int hs1 = hs0 + (N_SAMP / 4) - 1;
    s0 = max(s0, hs0);
    s1 = min(s1, hs1);
    if (s0 > s1) return;

    const uint2* tp = g_tabs + r.base;
    const int kn    = r.kn;
    const int M     = 1 + (kn >> 1) * TW;     // even-kn column multiplier

    float sum;
    if (kn & 1) sum = integrate<true >(tp, x0p, y0p, r.dxp, r.dyp, s0, s1, M, kn);
    else        sum = integrate<false>(tp, x0p, y0p, r.dxp, r.dyp, s0, s1, M, kn);

    const int o = (N_ANG - 1 - a) * N_DET + (N_DET - 1 - d);
    atomicAdd(out + o, sum * (1.0f / (float)N_SAMP));
}

extern "C" void kernel_launch(void* const* d_in, const int* in_sizes, int n_in,
                              void* d_out, int out_size)
{
    const float* img = (const float*)d_in[0];
    float* out = (float*)d_out;

    dim3 bt(32, 8);
    dim3 bg((TW + 31) / 32, (TW + 31) / 32);   // 17 x 17 tiles
    build_tables<<<bg, bt>>>(img, out);

    // 512 angles * 16 det-warps * 4 s-quarters = 32768 warps = 4096 blocks
    radon_fwd_kernel<<<4096, 256>>>(out);
}